// round 3
// baseline (speedup 1.0000x reference)
#include <cuda_runtime.h>
#include <cstdint>

#define T_LEN 4096
#define E_DIM 256
#define H_DIM 256
#define G_DIM 1024   // 4*H
#define L_TAGS 18
#define START_TAG 16
#define STOP_TAG 17
#define NEGV (-10000.0f)

// ---------------- device scratch (static: no allocations allowed) ----------
__device__ float g_pre[2][(size_t)T_LEN * G_DIM];   // pre-activations, fwd/bwd
__device__ float g_h[2][(size_t)T_LEN * H_DIM];     // hf / hb
__device__ float g_emit[(size_t)T_LEN * L_TAGS];    // emissions

// ---------------- small helpers -------------------------------------------
__device__ __forceinline__ unsigned long long ffma2(unsigned long long a,
                                                    unsigned long long b,
                                                    unsigned long long c) {
    unsigned long long d;
    asm("fma.rn.f32x2 %0, %1, %2, %3;" : "=l"(d) : "l"(a), "l"(b), "l"(c));
    return d;
}
__device__ __forceinline__ float2 unpackf2(unsigned long long v) {
    float2 r;
    asm("mov.b64 {%0, %1}, %2;" : "=f"(r.x), "=f"(r.y) : "l"(v));
    return r;
}
__device__ __forceinline__ float sigmoidf_(float x) {
    return __fdividef(1.0f, 1.0f + __expf(-x));
}
__device__ __forceinline__ float tanh_fast(float x) {
    float e = __expf(2.0f * x);
    return 1.0f - __fdividef(2.0f, e + 1.0f);
}
__device__ __forceinline__ uint32_t smem_u32(const void* p) {
    uint32_t a;
    asm("{ .reg .u64 t; cvta.to.shared.u64 t, %1; cvt.u32.u64 %0, t; }"
        : "=r"(a) : "l"(p));
    return a;
}
__device__ __forceinline__ uint32_t mapa_u32(uint32_t local, uint32_t rank) {
    uint32_t r;
    asm("mapa.shared::cluster.u32 %0, %1, %2;" : "=r"(r) : "r"(local), "r"(rank));
    return r;
}
__device__ __forceinline__ void st_cluster_16B(uint32_t addr,
                                               unsigned long long x,
                                               unsigned long long y) {
    asm volatile("st.shared::cluster.v2.u64 [%0], {%1, %2};"
                 :: "r"(addr), "l"(x), "l"(y) : "memory");
}
__device__ __forceinline__ void st_release_u32(uint32_t addr, unsigned v) {
    asm volatile("st.release.cluster.shared::cluster.b32 [%0], %1;"
                 :: "r"(addr), "r"(v) : "memory");
}
__device__ __forceinline__ unsigned ld_acquire_u32(uint32_t addr) {
    unsigned v;
    asm volatile("ld.acquire.cluster.shared::cta.b32 %0, [%1];"
                 : "=r"(v) : "r"(addr) : "memory");
    return v;
}

// ---------------- 1) fused gather + input GEMM -----------------------------
__global__ __launch_bounds__(256) void gemm_pre_kernel(
    const int* __restrict__ feats, const float* __restrict__ emb,
    const float* __restrict__ wih_f, const float* __restrict__ wih_b,
    const float* __restrict__ b_f, const float* __restrict__ b_b) {
    int dir = blockIdx.z;
    const float* wih  = dir ? wih_b : wih_f;
    const float* bias = dir ? b_b : b_f;
    float* out = g_pre[dir];

    int m0 = blockIdx.y * 64;   // time tile
    int n0 = blockIdx.x * 64;   // gate-row tile

    __shared__ __align__(16) float As[64][68];
    __shared__ __align__(16) float Bs[64][68];
    __shared__ int fid[64];

    int tid = threadIdx.x;
    int tx = tid & 15, ty = tid >> 4;

    if (tid < 64) fid[tid] = feats[m0 + tid];
    __syncthreads();

    float acc[4][4];
#pragma unroll
    for (int i = 0; i < 4; i++)
#pragma unroll
        for (int j = 0; j < 4; j++) acc[i][j] = 0.f;

    for (int kb = 0; kb < 4; kb++) {
#pragma unroll
        for (int i = 0; i < 16; i++) {
            int idx = tid + i * 256;
            int m = idx >> 6, k = idx & 63;
            As[k][m] = emb[(size_t)fid[m] * E_DIM + kb * 64 + k];
            Bs[k][m] = wih[(size_t)(n0 + m) * E_DIM + kb * 64 + k];
        }
        __syncthreads();
#pragma unroll
        for (int k = 0; k < 64; k++) {
            float4 a4 = *(const float4*)&As[k][ty * 4];
            float4 b4 = *(const float4*)&Bs[k][tx * 4];
            float av[4] = {a4.x, a4.y, a4.z, a4.w};
            float bv[4] = {b4.x, b4.y, b4.z, b4.w};
#pragma unroll
            for (int i = 0; i < 4; i++)
#pragma unroll
                for (int j = 0; j < 4; j++) acc[i][j] += av[i] * bv[j];
        }
        __syncthreads();
    }
#pragma unroll
    for (int j = 0; j < 4; j++) {
        float bj = bias[n0 + tx * 4 + j];
#pragma unroll
        for (int i = 0; i < 4; i++)
            out[(size_t)(m0 + ty * 4 + i) * G_DIM + n0 + tx * 4 + j] =
                acc[i][j] + bj;
    }
}

// ---------------- 2) LSTM recurrence: 8-CTA cluster per direction ----------
// Lane layout: lane = g(bits0-1) | gate(bits2-3) | u2(bit4).
// Producers stage h locally; after __syncthreads, warp 0 lanes 0-7 each ship
// the CTA's whole 128B h-block to one peer CTA (8 packed 16B stores) and
// publish ONE release-flag carrying the step number. Consumers acquire-poll
// the 8 flag words. No mbarrier atomics, no per-unit fan-out.
__global__ void __cluster_dims__(8, 1, 1) __launch_bounds__(512, 1)
lstm_cluster_kernel(const float* __restrict__ whh_f,
                    const float* __restrict__ whh_b) {
    __shared__ __align__(16) float hsm[2][272];   // padded h, double-buffered
    __shared__ __align__(16) float hstage[32];    // this CTA's 32 fresh h
    __shared__ __align__(16) unsigned int flags[8];

    uint32_t rank;
    asm("mov.u32 %0, %%cluster_ctarank;" : "=r"(rank));
    int dir = blockIdx.x >> 3;

    const float* whh = dir ? whh_b : whh_f;
    const float* pre = g_pre[dir];
    float* hout = g_h[dir];

    int tid = threadIdx.x;
    int lane = tid & 31, warp = tid >> 5;
    int g = lane & 3;              // column group [64g, 64g+64)
    int gate = (lane >> 2) & 3;    // i,f,g,o
    int u2 = lane >> 4;            // unit within warp pair
    int unit_local = warp * 2 + u2;           // 0..31
    int k_unit = (int)rank * 32 + unit_local; // global hidden unit
    int grow = gate * 256 + k_unit;           // global gate row

    // register-resident weights: 64 floats = 32 packed f32x2
    unsigned long long wr[32];
    {
        const ulonglong2* wp =
            (const ulonglong2*)(whh + (size_t)grow * H_DIM + g * 64);
#pragma unroll
        for (int q = 0; q < 16; q++) {
            ulonglong2 v = wp[q];
            wr[2 * q] = v.x;
            wr[2 * q + 1] = v.y;
        }
    }

    for (int i = tid; i < 272; i += 512) { hsm[0][i] = 0.f; hsm[1][i] = 0.f; }
    if (tid < 8) flags[tid] = 0u;

    uint32_t hbase = smem_u32(&hsm[0][0]);
    uint32_t fbase = smem_u32(&flags[0]);
    int remote_off = ((int)rank >> 1) * 68 + ((int)rank & 1) * 32;

    uint32_t dst0 = 0, dst1 = 0, fdst = 0, myflag = 0;
    if (warp == 0 && lane < 8) {
        dst0 = mapa_u32(hbase + (uint32_t)(remote_off) * 4u, (uint32_t)lane);
        dst1 = mapa_u32(hbase + (uint32_t)(272 + remote_off) * 4u, (uint32_t)lane);
        fdst = mapa_u32(fbase + (uint32_t)rank * 4u, (uint32_t)lane);
    }
    if (lane < 8) myflag = smem_u32(&flags[lane]);

    __syncthreads();
    asm volatile("barrier.cluster.arrive.aligned;" ::: "memory");
    asm volatile("barrier.cluster.wait.aligned;" ::: "memory");

    float c = 0.f;
    bool producer = ((lane & 15) == 0);

    // prologue prefetch of pre[t0]
    float p_cur = 0.f;
    if (g == 0) {
        int t0 = dir ? (T_LEN - 1) : 0;
        p_cur = __ldg(&pre[(size_t)t0 * G_DIM + grow]);
    }

    for (int s = 0; s < T_LEN; s++) {
        int t = dir ? (T_LEN - 1 - s) : s;
        int b = s & 1;

        // prefetch next step's pre (hides DRAM latency under this step)
        float p_next = 0.f;
        if (g == 0 && s + 1 < T_LEN) {
            int tn = dir ? (T_LEN - 2 - s) : (s + 1);
            p_next = __ldg(&pre[(size_t)tn * G_DIM + grow]);
        }

        // wait for all 8 source CTAs to have published step-s h
        if (s > 0) {
            for (;;) {
                unsigned v = (lane < 8) ? ld_acquire_u32(myflag) : 0x7fffffffu;
                if (__all_sync(0xffffffffu, v >= (unsigned)s)) break;
            }
        }

        // matvec: 64 weights vs h[64g .. 64g+64)
        const ulonglong2* h2 = (const ulonglong2*)(&hsm[b][g * 68]);
        unsigned long long acc0 = 0ull, acc1 = 0ull;
#pragma unroll
        for (int q = 0; q < 16; q++) {
            ulonglong2 hv = h2[q];
            acc0 = ffma2(wr[2 * q], hv.x, acc0);
            acc1 = ffma2(wr[2 * q + 1], hv.y, acc1);
        }
        float2 a0 = unpackf2(acc0), a1 = unpackf2(acc1);
        float sum = (a0.x + a0.y) + (a1.x + a1.y);
        sum += __shfl_xor_sync(0xffffffffu, sum, 1);
        sum += __shfl_xor_sync(0xffffffffu, sum, 2);
        if (g == 0) sum += p_cur;

        // gather the 4 gate sums of this half-warp's unit (g==0 lanes)
        int base = lane & 16;
        float gi = __shfl_sync(0xffffffffu, sum, base + 0);
        float gf = __shfl_sync(0xffffffffu, sum, base + 4);
        float gc = __shfl_sync(0xffffffffu, sum, base + 8);
        float go = __shfl_sync(0xffffffffu, sum, base + 12);

        if (producer) {
            float ii = sigmoidf_(gi), ff = sigmoidf_(gf), oo = sigmoidf_(go);
            c = ff * c + ii * tanh_fast(gc);
            float h = oo * tanh_fast(c);
            hstage[unit_local] = h;
            hout[(size_t)t * H_DIM + k_unit] = h;   // off critical path
        }
        __syncthreads();   // all producers staged; all reads of hsm[b] done

        // warp 0: ship the 128B block to every CTA, then publish flag = s+1
        if (warp == 0 && lane < 8) {
            uint32_t d = (b ? dst0 : dst1);   // writes go to buffer b^1
#pragma unroll
            for (int q = 0; q < 8; q++) {
                ulonglong2 x = *(const ulonglong2*)&hstage[q * 4];
                st_cluster_16B(d + (uint32_t)q * 16u, x.x, x.y);
            }
            st_release_u32(fdst, (unsigned)(s + 1));
        }
        p_cur = p_next;
    }

    // drain: seeing flag==T_LEN proves all data stores targeting us arrived
    for (;;) {
        unsigned v = (lane < 8) ? ld_acquire_u32(myflag) : 0x7fffffffu;
        if (__all_sync(0xffffffffu, v >= (unsigned)T_LEN)) break;
    }
    asm volatile("barrier.cluster.arrive.aligned;" ::: "memory");
    asm volatile("barrier.cluster.wait.aligned;" ::: "memory");
}

// ---------------- 3) emit = [hf|hb] @ W_out.T + b_out ----------------------
__global__ __launch_bounds__(128) void emit_kernel(
    const float* __restrict__ Wout, const float* __restrict__ bout) {
    int t = blockIdx.x;
    __shared__ float h[512];
    __shared__ float part[4][18];
    int tid = threadIdx.x;

    h[tid]       = g_h[0][(size_t)t * 256 + tid];
    h[tid + 128] = g_h[0][(size_t)t * 256 + 128 + tid];
    h[tid + 256] = g_h[1][(size_t)t * 256 + tid];
    h[tid + 384] = g_h[1][(size_t)t * 256 + 128 + tid];
    __syncthreads();

    if (tid < 72) {
        int jj = tid >> 2, q = tid & 3;
        const float* w = Wout + (size_t)jj * 512 + q * 128;
        const float* hh = h + q * 128;
        float a0 = 0.f, a1 = 0.f, a2 = 0.f, a3 = 0.f;
#pragma unroll
        for (int k = 0; k < 128; k += 4) {
            a0 += hh[k] * w[k];
            a1 += hh[k + 1] * w[k + 1];
            a2 += hh[k + 2] * w[k + 2];
            a3 += hh[k + 3] * w[k + 3];
        }
        part[q][jj] = (a0 + a1) + (a2 + a3);
    }
    __syncthreads();
    if (tid < 18)
        g_emit[(size_t)t * L_TAGS + tid] =
            part[0][tid] + part[1][tid] + part[2][tid] + part[3][tid] + bout[tid];
}

// ---------------- 4) Viterbi + backtrack (one warp) -------------------------
__global__ void viterbi_kernel(const float* __restrict__ trans,
                               float* __restrict__ out, int write_score) {
    extern __shared__ unsigned char bp[];   // T_LEN * L_TAGS backpointers
    int j = threadIdx.x;
    bool act = (j < L_TAGS);

    float tcol[L_TAGS];
#pragma unroll
    for (int i = 0; i < L_TAGS; i++)
        tcol[i] = act ? trans[i * L_TAGS + j] : 0.f;

    float fv = act ? ((j == START_TAG) ? 0.f : NEGV) : -3.0e38f;
    float e = act ? g_emit[j] : 0.f;

    for (int t = 0; t < T_LEN; t++) {
        float e_next = (act && t + 1 < T_LEN)
                           ? g_emit[(size_t)(t + 1) * L_TAGS + j] : 0.f;
        float b0 = -3.4e38f, b1 = -3.4e38f, b2 = -3.4e38f;
        int a0 = 0, a1 = 6, a2 = 12;
#pragma unroll
        for (int i = 0; i < 6; i++) {
            float s0 = __shfl_sync(0xffffffffu, fv, i) + tcol[i];
            float s1 = __shfl_sync(0xffffffffu, fv, i + 6) + tcol[i + 6];
            float s2 = __shfl_sync(0xffffffffu, fv, i + 12) + tcol[i + 12];
            if (s0 > b0) { b0 = s0; a0 = i; }
            if (s1 > b1) { b1 = s1; a1 = i + 6; }
            if (s2 > b2) { b2 = s2; a2 = i + 12; }
        }
        float best = b0; int arg = a0;
        if (b1 > best) { best = b1; arg = a1; }
        if (b2 > best) { best = b2; arg = a2; }

        if (act) {
            bp[t * L_TAGS + j] = (unsigned char)arg;
            fv = best + e;
        }
        e = e_next;
    }

    float term = act ? (fv + trans[j * L_TAGS + STOP_TAG]) : -3.4e38f;
    int ai = j;
#pragma unroll
    for (int off = 16; off > 0; off >>= 1) {
        float ov = __shfl_xor_sync(0xffffffffu, term, off);
        int oi = __shfl_xor_sync(0xffffffffu, ai, off);
        if (ov > term || (ov == term && oi < ai)) { term = ov; ai = oi; }
    }

    if (j == 0) {
        if (write_score) out[0] = term;
        float* path = out + write_score;
        int tag = ai;
        for (int t = T_LEN - 1; t >= 0; t--) {
            path[t] = (float)tag;
            tag = bp[t * L_TAGS + tag];
        }
    }
}

// ---------------- launch ----------------------------------------------------
extern "C" void kernel_launch(void* const* d_in, const int* in_sizes, int n_in,
                              void* d_out, int out_size) {
    const int*   feats  = (const int*)d_in[0];
    const float* emb    = (const float*)d_in[1];
    const float* w_ih_f = (const float*)d_in[2];
    const float* w_hh_f = (const float*)d_in[3];
    const float* b_f    = (const float*)d_in[4];
    const float* w_ih_b = (const float*)d_in[5];
    const float* w_hh_b = (const float*)d_in[6];
    const float* b_b    = (const float*)d_in[7];
    const float* W_out  = (const float*)d_in[8];
    const float* b_out  = (const float*)d_in[9];
    const float* trans  = (const float*)d_in[10];

    dim3 gg(G_DIM / 64, T_LEN / 64, 2);
    gemm_pre_kernel<<<gg, 256>>>(feats, emb, w_ih_f, w_ih_b, b_f, b_b);

    lstm_cluster_kernel<<<16, 512>>>(w_hh_f, w_hh_b);

    emit_kernel<<<T_LEN, 128>>>(W_out, b_out);

    int ws = (out_size > T_LEN) ? 1 : 0;   // layout: [path_score, path...]
    static int smem_set = 0;
    if (!smem_set) {
        cudaFuncSetAttribute(viterbi_kernel,
                             cudaFuncAttributeMaxDynamicSharedMemorySize,
                             T_LEN * L_TAGS + 1024);
        smem_set = 1;
    }
    viterbi_kernel<<<1, 32, T_LEN * L_TAGS>>>(trans, (float*)d_out, ws);
}

// round 4
// speedup vs baseline: 1.0256x; 1.0256x over previous
#include <cuda_runtime.h>
#include <cstdint>

#define T_LEN 4096
#define E_DIM 256
#define H_DIM 256
#define G_DIM 1024   // 4*H
#define L_TAGS 18
#define START_TAG 16
#define STOP_TAG 17
#define NEGV (-10000.0f)

// ---------------- device scratch (static: no allocations allowed) ----------
__device__ float g_pre[2][(size_t)T_LEN * G_DIM];   // pre-activations, fwd/bwd
__device__ float g_h[2][(size_t)T_LEN * H_DIM];     // hf / hb
__device__ float g_emit[(size_t)T_LEN * L_TAGS];    // emissions

// ---------------- small helpers -------------------------------------------
__device__ __forceinline__ unsigned long long ffma2(unsigned long long a,
                                                    unsigned long long b,
                                                    unsigned long long c) {
    unsigned long long d;
    asm("fma.rn.f32x2 %0, %1, %2, %3;" : "=l"(d) : "l"(a), "l"(b), "l"(c));
    return d;
}
__device__ __forceinline__ float2 unpackf2(unsigned long long v) {
    float2 r;
    asm("mov.b64 {%0, %1}, %2;" : "=f"(r.x), "=f"(r.y) : "l"(v));
    return r;
}
__device__ __forceinline__ float sigmoidf_(float x) {
    return __fdividef(1.0f, 1.0f + __expf(-x));
}
__device__ __forceinline__ float tanh_fast(float x) {
    float e = __expf(2.0f * x);
    return 1.0f - __fdividef(2.0f, e + 1.0f);
}
__device__ __forceinline__ uint32_t smem_u32(const void* p) {
    uint32_t a;
    asm("{ .reg .u64 t; cvta.to.shared.u64 t, %1; cvt.u32.u64 %0, t; }"
        : "=r"(a) : "l"(p));
    return a;
}
__device__ __forceinline__ uint32_t mapa_u32(uint32_t local, uint32_t rank) {
    uint32_t r;
    asm("mapa.shared::cluster.u32 %0, %1, %2;" : "=r"(r) : "r"(local), "r"(rank));
    return r;
}
__device__ __forceinline__ void st_cluster_16B(uint32_t addr,
                                               unsigned long long x,
                                               unsigned long long y) {
    asm volatile("st.shared::cluster.v2.u64 [%0], {%1, %2};"
                 :: "r"(addr), "l"(x), "l"(y) : "memory");
}
__device__ __forceinline__ void mbar_init(uint32_t mbar, uint32_t count) {
    asm volatile("mbarrier.init.shared::cta.b64 [%0], %1;" :: "r"(mbar), "r"(count)
                 : "memory");
}
__device__ __forceinline__ void mbar_arrive_remote(uint32_t mbar) {
    asm volatile("mbarrier.arrive.release.cluster.shared::cluster.b64 _, [%0];"
                 :: "r"(mbar) : "memory");
}
__device__ __forceinline__ void mbar_wait(uint32_t mbar, uint32_t parity) {
    asm volatile(
        "{\n\t.reg .pred P;\n\t"
        "W_%=:\n\t"
        "mbarrier.try_wait.parity.acquire.cluster.shared::cta.b64 P, [%0], %1;\n\t"
        "@P bra.uni D_%=;\n\t"
        "bra.uni W_%=;\n\t"
        "D_%=:\n\t}"
        :: "r"(mbar), "r"(parity) : "memory");
}

// ---------------- 1) fused gather + input GEMM -----------------------------
__global__ __launch_bounds__(256) void gemm_pre_kernel(
    const int* __restrict__ feats, const float* __restrict__ emb,
    const float* __restrict__ wih_f, const float* __restrict__ wih_b,
    const float* __restrict__ b_f, const float* __restrict__ b_b) {
    int dir = blockIdx.z;
    const float* wih  = dir ? wih_b : wih_f;
    const float* bias = dir ? b_b : b_f;
    float* out = g_pre[dir];

    int m0 = blockIdx.y * 64;   // time tile
    int n0 = blockIdx.x * 64;   // gate-row tile

    __shared__ __align__(16) float As[64][68];
    __shared__ __align__(16) float Bs[64][68];
    __shared__ int fid[64];

    int tid = threadIdx.x;
    int tx = tid & 15, ty = tid >> 4;

    if (tid < 64) fid[tid] = feats[m0 + tid];
    __syncthreads();

    float acc[4][4];
#pragma unroll
    for (int i = 0; i < 4; i++)
#pragma unroll
        for (int j = 0; j < 4; j++) acc[i][j] = 0.f;

    for (int kb = 0; kb < 4; kb++) {
#pragma unroll
        for (int i = 0; i < 16; i++) {
            int idx = tid + i * 256;
            int m = idx >> 6, k = idx & 63;
            As[k][m] = emb[(size_t)fid[m] * E_DIM + kb * 64 + k];
            Bs[k][m] = wih[(size_t)(n0 + m) * E_DIM + kb * 64 + k];
        }
        __syncthreads();
#pragma unroll
        for (int k = 0; k < 64; k++) {
            float4 a4 = *(const float4*)&As[k][ty * 4];
            float4 b4 = *(const float4*)&Bs[k][tx * 4];
            float av[4] = {a4.x, a4.y, a4.z, a4.w};
            float bv[4] = {b4.x, b4.y, b4.z, b4.w};
#pragma unroll
            for (int i = 0; i < 4; i++)
#pragma unroll
                for (int j = 0; j < 4; j++) acc[i][j] += av[i] * bv[j];
        }
        __syncthreads();
    }
#pragma unroll
    for (int j = 0; j < 4; j++) {
        float bj = bias[n0 + tx * 4 + j];
#pragma unroll
        for (int i = 0; i < 4; i++)
            out[(size_t)(m0 + ty * 4 + i) * G_DIM + n0 + tx * 4 + j] =
                acc[i][j] + bj;
    }
}

// ---------------- 2) LSTM recurrence: 8-CTA cluster per direction ----------
// Lane layout: lane = g(bits0-1) | gate(bits2-3) | u2(bit4).
// Per step: producers stage 32 fresh h into hstage; __syncthreads; warp 0
// lanes 0-7 each ship the whole 128B block to ONE peer CTA (8 x 16B cluster
// stores) and issue a single release-arrive on that peer's buffer mbarrier
// (count=8: one arrive per source CTA). Consumers sleep in try_wait.
// => 8 mbarrier RMWs per CTA per step instead of 256.
__global__ void __cluster_dims__(8, 1, 1) __launch_bounds__(512, 1)
lstm_cluster_kernel(const float* __restrict__ whh_f,
                    const float* __restrict__ whh_b) {
    __shared__ __align__(16) float hsm[2][272];   // padded h, double-buffered
    __shared__ __align__(16) float hstage[32];    // this CTA's 32 fresh h
    __shared__ __align__(8) unsigned long long mbar_sm[2];

    uint32_t rank;
    asm("mov.u32 %0, %%cluster_ctarank;" : "=r"(rank));
    int dir = blockIdx.x >> 3;

    const float* whh = dir ? whh_b : whh_f;
    const float* pre = g_pre[dir];
    float* hout = g_h[dir];

    int tid = threadIdx.x;
    int lane = tid & 31, warp = tid >> 5;
    int g = lane & 3;              // column group [64g, 64g+64)
    int gate = (lane >> 2) & 3;    // i,f,g,o
    int u2 = lane >> 4;            // unit within warp pair
    int unit_local = warp * 2 + u2;           // 0..31
    int k_unit = (int)rank * 32 + unit_local; // global hidden unit
    int grow = gate * 256 + k_unit;           // global gate row

    // register-resident weights: 64 floats = 32 packed f32x2
    unsigned long long wr[32];
    {
        const ulonglong2* wp =
            (const ulonglong2*)(whh + (size_t)grow * H_DIM + g * 64);
#pragma unroll
        for (int q = 0; q < 16; q++) {
            ulonglong2 v = wp[q];
            wr[2 * q] = v.x;
            wr[2 * q + 1] = v.y;
        }
    }

    for (int i = tid; i < 272; i += 512) { hsm[0][i] = 0.f; hsm[1][i] = 0.f; }

    uint32_t hbase = smem_u32(&hsm[0][0]);
    uint32_t mb0 = smem_u32(&mbar_sm[0]);
    uint32_t mb1 = smem_u32(&mbar_sm[1]);

    if (tid == 0) { mbar_init(mb0, 8); mbar_init(mb1, 8); }

    // sender setup: my units land at padded offset off(rank) in every CTA
    int remote_off = ((int)rank >> 1) * 68 + ((int)rank & 1) * 32;
    uint32_t dst_b0 = 0, dst_b1 = 0, mdst0 = 0, mdst1 = 0;
    if (warp == 0 && lane < 8) {
        dst_b0 = mapa_u32(hbase + (uint32_t)remote_off * 4u, (uint32_t)lane);
        dst_b1 = mapa_u32(hbase + (uint32_t)(272 + remote_off) * 4u, (uint32_t)lane);
        mdst0 = mapa_u32(mb0, (uint32_t)lane);
        mdst1 = mapa_u32(mb1, (uint32_t)lane);
    }

    __syncthreads();
    asm volatile("barrier.cluster.arrive.aligned;" ::: "memory");
    asm volatile("barrier.cluster.wait.aligned;" ::: "memory");

    float c = 0.f;
    bool producer = ((lane & 15) == 0);
    uint32_t par0 = 0, par1 = 0;

    // prologue prefetch of pre[t0]
    float p_cur = 0.f;
    if (g == 0) {
        int t0 = dir ? (T_LEN - 1) : 0;
        p_cur = __ldg(&pre[(size_t)t0 * G_DIM + grow]);
    }

    for (int s = 0; s < T_LEN; s++) {
        int t = dir ? (T_LEN - 1 - s) : s;
        int b = s & 1;

        // prefetch next step's pre (hides DRAM latency under this step)
        float p_next = 0.f;
        if (g == 0 && s + 1 < T_LEN) {
            int tn = dir ? (T_LEN - 2 - s) : (s + 1);
            p_next = __ldg(&pre[(size_t)tn * G_DIM + grow]);
        }

        // wait until all 8 source CTAs delivered h for this step
        if (s > 0) {
            if (b) { mbar_wait(mb1, par1); par1 ^= 1; }
            else   { mbar_wait(mb0, par0); par0 ^= 1; }
        }

        // matvec: 64 weights vs h[64g .. 64g+64), 4 parallel FMA chains
        const ulonglong2* h2 = (const ulonglong2*)(&hsm[b][g * 68]);
        unsigned long long a0 = 0ull, a1 = 0ull, a2 = 0ull, a3 = 0ull;
#pragma unroll
        for (int q = 0; q < 8; q++) {
            ulonglong2 hv0 = h2[q];
            ulonglong2 hv1 = h2[q + 8];
            a0 = ffma2(wr[2 * q], hv0.x, a0);
            a1 = ffma2(wr[2 * q + 1], hv0.y, a1);
            a2 = ffma2(wr[2 * q + 16], hv1.x, a2);
            a3 = ffma2(wr[2 * q + 17], hv1.y, a3);
        }
        float2 f0 = unpackf2(a0), f1 = unpackf2(a1);
        float2 f2 = unpackf2(a2), f3 = unpackf2(a3);
        float sum = ((f0.x + f0.y) + (f1.x + f1.y)) +
                    ((f2.x + f2.y) + (f3.x + f3.y));
        sum += __shfl_xor_sync(0xffffffffu, sum, 1);
        sum += __shfl_xor_sync(0xffffffffu, sum, 2);
        if (g == 0) sum += p_cur;

        // gather the 4 gate sums of this half-warp's unit (g==0 lanes)
        int base = lane & 16;
        float gi = __shfl_sync(0xffffffffu, sum, base + 0);
        float gf = __shfl_sync(0xffffffffu, sum, base + 4);
        float gc = __shfl_sync(0xffffffffu, sum, base + 8);
        float go = __shfl_sync(0xffffffffu, sum, base + 12);

        if (producer) {
            float ii = sigmoidf_(gi), ff = sigmoidf_(gf), oo = sigmoidf_(go);
            c = ff * c + ii * tanh_fast(gc);
            float h = oo * tanh_fast(c);
            hstage[unit_local] = h;
            hout[(size_t)t * H_DIM + k_unit] = h;   // off critical path
        }
        __syncthreads();   // producers staged; all reads of hsm[b] retired

        // warp 0 lanes 0-7: ship 128B block to CTA 'lane', one arrive each
        if (warp == 0 && lane < 8) {
            const ulonglong2* st2 = (const ulonglong2*)hstage;
            uint32_t d = b ? dst_b0 : dst_b1;   // step-s output -> buffer b^1
            uint32_t m = b ? mdst0 : mdst1;
#pragma unroll
            for (int q = 0; q < 8; q++) {
                ulonglong2 x = st2[q];          // broadcast LDS.128
                st_cluster_16B(d + (uint32_t)q * 16u, x.x, x.y);
            }
            mbar_arrive_remote(m);              // orders this lane's stores
        }
        p_cur = p_next;
    }

    // drain: final sends (step T-1, odd) targeted mbar0; complete that phase
    mbar_wait(mb0, par0);
    asm volatile("barrier.cluster.arrive.aligned;" ::: "memory");
    asm volatile("barrier.cluster.wait.aligned;" ::: "memory");
}

// ---------------- 3) emit = [hf|hb] @ W_out.T + b_out ----------------------
__global__ __launch_bounds__(128) void emit_kernel(
    const float* __restrict__ Wout, const float* __restrict__ bout) {
    int t = blockIdx.x;
    __shared__ float h[512];
    __shared__ float part[4][18];
    int tid = threadIdx.x;

    h[tid]       = g_h[0][(size_t)t * 256 + tid];
    h[tid + 128] = g_h[0][(size_t)t * 256 + 128 + tid];
    h[tid + 256] = g_h[1][(size_t)t * 256 + tid];
    h[tid + 384] = g_h[1][(size_t)t * 256 + 128 + tid];
    __syncthreads();

    if (tid < 72) {
        int jj = tid >> 2, q = tid & 3;
        const float* w = Wout + (size_t)jj * 512 + q * 128;
        const float* hh = h + q * 128;
        float a0 = 0.f, a1 = 0.f, a2 = 0.f, a3 = 0.f;
#pragma unroll
        for (int k = 0; k < 128; k += 4) {
            a0 += hh[k] * w[k];
            a1 += hh[k + 1] * w[k + 1];
            a2 += hh[k + 2] * w[k + 2];
            a3 += hh[k + 3] * w[k + 3];
        }
        part[q][jj] = (a0 + a1) + (a2 + a3);
    }
    __syncthreads();
    if (tid < 18)
        g_emit[(size_t)t * L_TAGS + tid] =
            part[0][tid] + part[1][tid] + part[2][tid] + part[3][tid] + bout[tid];
}

// ---------------- 4) Viterbi + backtrack (one warp) -------------------------
__global__ void viterbi_kernel(const float* __restrict__ trans,
                               float* __restrict__ out, int write_score) {
    extern __shared__ unsigned char bp[];   // T_LEN * L_TAGS backpointers
    int j = threadIdx.x;
    bool act = (j < L_TAGS);

    float tcol[L_TAGS];
#pragma unroll
    for (int i = 0; i < L_TAGS; i++)
        tcol[i] = act ? trans[i * L_TAGS + j] : 0.f;

    float fv = act ? ((j == START_TAG) ? 0.f : NEGV) : -3.0e38f;
    float e = act ? g_emit[j] : 0.f;

    for (int t = 0; t < T_LEN; t++) {
        float e_next = (act && t + 1 < T_LEN)
                           ? g_emit[(size_t)(t + 1) * L_TAGS + j] : 0.f;
        float b0 = -3.4e38f, b1 = -3.4e38f, b2 = -3.4e38f;
        int a0 = 0, a1 = 6, a2 = 12;
#pragma unroll
        for (int i = 0; i < 6; i++) {
            float s0 = __shfl_sync(0xffffffffu, fv, i) + tcol[i];
            float s1 = __shfl_sync(0xffffffffu, fv, i + 6) + tcol[i + 6];
            float s2 = __shfl_sync(0xffffffffu, fv, i + 12) + tcol[i + 12];
            if (s0 > b0) { b0 = s0; a0 = i; }
            if (s1 > b1) { b1 = s1; a1 = i + 6; }
            if (s2 > b2) { b2 = s2; a2 = i + 12; }
        }
        float best = b0; int arg = a0;
        if (b1 > best) { best = b1; arg = a1; }
        if (b2 > best) { best = b2; arg = a2; }

        if (act) {
            bp[t * L_TAGS + j] = (unsigned char)arg;
            fv = best + e;
        }
        e = e_next;
    }

    float term = act ? (fv + trans[j * L_TAGS + STOP_TAG]) : -3.4e38f;
    int ai = j;
#pragma unroll
    for (int off = 16; off > 0; off >>= 1) {
        float ov = __shfl_xor_sync(0xffffffffu, term, off);
        int oi = __shfl_xor_sync(0xffffffffu, ai, off);
        if (ov > term || (ov == term && oi < ai)) { term = ov; ai = oi; }
    }

    if (j == 0) {
        if (write_score) out[0] = term;
        float* path = out + write_score;
        int tag = ai;
        for (int t = T_LEN - 1; t >= 0; t--) {
            path[t] = (float)tag;
            tag = bp[t * L_TAGS + tag];
        }
    }
}

// ---------------- launch ----------------------------------------------------
extern "C" void kernel_launch(void* const* d_in, const int* in_sizes, int n_in,
                              void* d_out, int out_size) {
    const int*   feats  = (const int*)d_in[0];
    const float* emb    = (const float*)d_in[1];
    const float* w_ih_f = (const float*)d_in[2];
    const float* w_hh_f = (const float*)d_in[3];
    const float* b_f    = (const float*)d_in[4];
    const float* w_ih_b = (const float*)d_in[5];
    const float* w_hh_b = (const float*)d_in[6];
    const float* b_b    = (const float*)d_in[7];
    const float* W_out  = (const float*)d_in[8];
    const float* b_out  = (const float*)d_in[9];
    const float* trans  = (const float*)d_in[10];

    dim3 gg(G_DIM / 64, T_LEN / 64, 2);
    gemm_pre_kernel<<<gg, 256>>>(feats, emb, w_ih_f, w_ih_b, b_f, b_b);

    lstm_cluster_kernel<<<16, 512>>>(w_hh_f, w_hh_b);

    emit_kernel<<<T_LEN, 128>>>(W_out, b_out);

    int ws = (out_size > T_LEN) ? 1 : 0;   // layout: [path_score, path...]
    static int smem_set = 0;
    if (!smem_set) {
        cudaFuncSetAttribute(viterbi_kernel,
                             cudaFuncAttributeMaxDynamicSharedMemorySize,
                             T_LEN * L_TAGS + 1024);
        smem_set = 1;
    }
    viterbi_kernel<<<1, 32, T_LEN * L_TAGS>>>(trans, (float*)d_out, ws);
}

// round 5
// speedup vs baseline: 1.3164x; 1.2835x over previous
#include <cuda_runtime.h>
#include <cstdint>

#define T_LEN 4096
#define E_DIM 256
#define H_DIM 256
#define G_DIM 1024   // 4*H
#define L_TAGS 18
#define START_TAG 16
#define STOP_TAG 17
#define NEGV (-10000.0f)

// ---------------- device scratch (static: no allocations allowed) ----------
__device__ float g_pre[2][(size_t)T_LEN * G_DIM];   // pre-activations, fwd/bwd
__device__ float g_h[2][(size_t)T_LEN * H_DIM];     // hf / hb
__device__ float g_emit[(size_t)T_LEN * L_TAGS];    // emissions

// ---------------- small helpers -------------------------------------------
__device__ __forceinline__ unsigned long long ffma2(unsigned long long a,
                                                    unsigned long long b,
                                                    unsigned long long c) {
    unsigned long long d;
    asm("fma.rn.f32x2 %0, %1, %2, %3;" : "=l"(d) : "l"(a), "l"(b), "l"(c));
    return d;
}
__device__ __forceinline__ float2 unpackf2(unsigned long long v) {
    float2 r;
    asm("mov.b64 {%0, %1}, %2;" : "=f"(r.x), "=f"(r.y) : "l"(v));
    return r;
}
__device__ __forceinline__ float sigmoidf_(float x) {
    return __fdividef(1.0f, 1.0f + __expf(-x));
}
__device__ __forceinline__ float tanh_fast(float x) {
    float e = __expf(2.0f * x);
    return 1.0f - __fdividef(2.0f, e + 1.0f);
}
__device__ __forceinline__ uint32_t smem_u32(const void* p) {
    uint32_t a;
    asm("{ .reg .u64 t; cvta.to.shared.u64 t, %1; cvt.u32.u64 %0, t; }"
        : "=r"(a) : "l"(p));
    return a;
}
__device__ __forceinline__ uint32_t mapa_u32(uint32_t local, uint32_t rank) {
    uint32_t r;
    asm("mapa.shared::cluster.u32 %0, %1, %2;" : "=r"(r) : "r"(local), "r"(rank));
    return r;
}
__device__ __forceinline__ void mbar_init(uint32_t mbar, uint32_t count) {
    asm volatile("mbarrier.init.shared::cta.b64 [%0], %1;" :: "r"(mbar), "r"(count)
                 : "memory");
}
__device__ __forceinline__ void mbar_expect_tx(uint32_t mbar, uint32_t bytes) {
    asm volatile("mbarrier.arrive.expect_tx.shared::cta.b64 _, [%0], %1;"
                 :: "r"(mbar), "r"(bytes) : "memory");
}
// HW-sleep wait: try_wait WITH suspend-time hint (this is the documented
// sleeping form; the hint-less form is a busy poll that hammers the LSU).
__device__ __forceinline__ void mbar_wait(uint32_t mbar, uint32_t parity) {
    asm volatile(
        "{\n\t.reg .pred P;\n\t"
        "W_%=:\n\t"
        "mbarrier.try_wait.parity.acquire.cta.shared::cta.b64 P, [%0], %1, 0x989680;\n\t"
        "@P bra.uni D_%=;\n\t"
        "bra.uni W_%=;\n\t"
        "D_%=:\n\t}"
        :: "r"(mbar), "r"(parity) : "memory");
}
__device__ __forceinline__ void st_async_b64(uint32_t addr, unsigned long long v,
                                             uint32_t mbar) {
    asm volatile(
        "st.async.shared::cluster.mbarrier::complete_tx::bytes.b64 [%0], %1, [%2];"
        :: "r"(addr), "l"(v), "r"(mbar) : "memory");
}
__device__ __forceinline__ void cp_async16(uint32_t dst, const void* src) {
    asm volatile("cp.async.ca.shared.global [%0], [%1], 16;"
                 :: "r"(dst), "l"(src) : "memory");
}

// ---------------- 1) fused gather + input GEMM -----------------------------
__global__ __launch_bounds__(256) void gemm_pre_kernel(
    const int* __restrict__ feats, const float* __restrict__ emb,
    const float* __restrict__ wih_f, const float* __restrict__ wih_b,
    const float* __restrict__ b_f, const float* __restrict__ b_b) {
    int dir = blockIdx.z;
    const float* wih  = dir ? wih_b : wih_f;
    const float* bias = dir ? b_b : b_f;
    float* out = g_pre[dir];

    int m0 = blockIdx.y * 64;   // time tile
    int n0 = blockIdx.x * 64;   // gate-row tile

    __shared__ __align__(16) float As[64][68];
    __shared__ __align__(16) float Bs[64][68];
    __shared__ int fid[64];

    int tid = threadIdx.x;
    int tx = tid & 15, ty = tid >> 4;

    if (tid < 64) fid[tid] = feats[m0 + tid];
    __syncthreads();

    float acc[4][4];
#pragma unroll
    for (int i = 0; i < 4; i++)
#pragma unroll
        for (int j = 0; j < 4; j++) acc[i][j] = 0.f;

    for (int kb = 0; kb < 4; kb++) {
#pragma unroll
        for (int i = 0; i < 16; i++) {
            int idx = tid + i * 256;
            int m = idx >> 6, k = idx & 63;
            As[k][m] = emb[(size_t)fid[m] * E_DIM + kb * 64 + k];
            Bs[k][m] = wih[(size_t)(n0 + m) * E_DIM + kb * 64 + k];
        }
        __syncthreads();
#pragma unroll
        for (int k = 0; k < 64; k++) {
            float4 a4 = *(const float4*)&As[k][ty * 4];
            float4 b4 = *(const float4*)&Bs[k][tx * 4];
            float av[4] = {a4.x, a4.y, a4.z, a4.w};
            float bv[4] = {b4.x, b4.y, b4.z, b4.w};
#pragma unroll
            for (int i = 0; i < 4; i++)
#pragma unroll
                for (int j = 0; j < 4; j++) acc[i][j] += av[i] * bv[j];
        }
        __syncthreads();
    }
#pragma unroll
    for (int j = 0; j < 4; j++) {
        float bj = bias[n0 + tx * 4 + j];
#pragma unroll
        for (int i = 0; i < 4; i++)
            out[(size_t)(m0 + ty * 4 + i) * G_DIM + n0 + tx * 4 + j] =
                acc[i][j] + bj;
    }
}

// ---------------- 2) LSTM recurrence: 8-CTA cluster per direction ----------
// R2 structure (st.async fan-out + tx mbarriers, empirically best) plus:
//  - HW-sleep mbarrier waits (suspend hint) -> no poll traffic on the LSU
//  - pre[] streamed into SMEM via cp.async, 16-step chunks, 3-buffer ring
//  - pair-packed b64 sends: one st.async per warp per target (128/step/CTA)
__global__ void __cluster_dims__(8, 1, 1) __launch_bounds__(512, 1)
lstm_cluster_kernel(const float* __restrict__ whh_f,
                    const float* __restrict__ whh_b) {
    __shared__ __align__(16) float hsm[2][272];        // padded h, dbl-buffered
    __shared__ __align__(16) float pre_s[3][16][144];  // 16 steps x 4x36
    __shared__ __align__(8) unsigned long long mbar_sm[2];

    uint32_t rank;
    asm("mov.u32 %0, %%cluster_ctarank;" : "=r"(rank));
    int dir = blockIdx.x >> 3;

    const float* whh = dir ? whh_b : whh_f;
    const float* pre = g_pre[dir];
    float* hout = g_h[dir];

    int tid = threadIdx.x;
    int lane = tid & 31, warp = tid >> 5;
    int g = lane & 3;              // column group [64g, 64g+64)
    int gate = (lane >> 2) & 3;    // i,f,g,o
    int u2 = lane >> 4;            // unit within warp pair
    int unit_local = warp * 2 + u2;           // 0..31
    int k_unit = (int)rank * 32 + unit_local; // global hidden unit
    int grow = gate * 256 + k_unit;           // global gate row

    // register-resident weights: 64 floats = 32 packed f32x2
    unsigned long long wr[32];
    {
        const ulonglong2* wp =
            (const ulonglong2*)(whh + (size_t)grow * H_DIM + g * 64);
#pragma unroll
        for (int q = 0; q < 16; q++) {
            ulonglong2 v = wp[q];
            wr[2 * q] = v.x;
            wr[2 * q + 1] = v.y;
        }
    }

    for (int i = tid; i < 272; i += 512) { hsm[0][i] = 0.f; hsm[1][i] = 0.f; }

    uint32_t hbase = smem_u32(&hsm[0][0]);
    uint32_t pbase = smem_u32(&pre_s[0][0][0]);
    uint32_t mb0 = smem_u32(&mbar_sm[0]);
    uint32_t mb1 = smem_u32(&mbar_sm[1]);

    if (tid == 0) {
        mbar_init(mb0, 1);
        mbar_init(mb1, 1);
        mbar_expect_tx(mb1, 1024);   // stores made during step 0 land on mb1
    }

    // --- pre[] chunk loader lane mapping (1 x 16B per thread per chunk) ---
    int c_step = tid >> 5;          // 0..15: step within chunk
    int c_sub = tid & 31;
    int c_gate = c_sub >> 3, c_l8 = c_sub & 7;

    // prologue: issue chunks 0 and 1
#pragma unroll
    for (int ck = 0; ck < 2; ck++) {
        int ss = ck * 16 + c_step;
        int t = dir ? (T_LEN - 1 - ss) : ss;
        const float* src =
            pre + (size_t)t * G_DIM + c_gate * 256 + (int)rank * 32 + c_l8 * 4;
        uint32_t dst = pbase +
            (uint32_t)((ck * 16 + c_step) * 144 + c_gate * 36 + c_l8 * 4) * 4u;
        cp_async16(dst, src);
        asm volatile("cp.async.commit_group;" ::: "memory");
    }

    __syncthreads();
    asm volatile("barrier.cluster.arrive.aligned;" ::: "memory");
    asm volatile("barrier.cluster.wait.aligned;" ::: "memory");

    float c = 0.f;
    bool producer = ((lane & 15) == 0);
    uint32_t par0 = 0, par1 = 0;

    // sender slot (lane 0 of each warp ships units {2w, 2w+1} as one b64)
    int k_even = (int)rank * 32 + warp * 2;
    int koff = ((k_even >> 6) * 68) + (k_even & 63);

    for (int s = 0; s < T_LEN; s++) {
        int b = s & 1;
        int si = s & 15;
        int t = dir ? (T_LEN - 1 - s) : s;

        if (si == 0) {
            int c2 = (s >> 4) + 2;
            if (c2 < (T_LEN / 16)) {
                int ss = c2 * 16 + c_step;
                int tt = dir ? (T_LEN - 1 - ss) : ss;
                const float* src = pre + (size_t)tt * G_DIM + c_gate * 256 +
                                   (int)rank * 32 + c_l8 * 4;
                uint32_t dst = pbase +
                    (uint32_t)(((c2 % 3) * 16 + c_step) * 144 +
                               c_gate * 36 + c_l8 * 4) * 4u;
                cp_async16(dst, src);
                asm volatile("cp.async.commit_group;" ::: "memory");
                asm volatile("cp.async.wait_group 2;" ::: "memory");
            } else {
                asm volatile("cp.async.wait_group 0;" ::: "memory");
            }
            __syncthreads();
        }
        int buf = (s >> 4) % 3;

        // pre value from SMEM (independent of h; read before the wait)
        float p = 0.f;
        if (g == 0) p = pre_s[buf][si][gate * 36 + unit_local];

        // wait until all 8 source CTAs delivered h for this step (HW sleep)
        if (s > 0) {
            if (b) { mbar_wait(mb1, par1); par1 ^= 1; }
            else   { mbar_wait(mb0, par0); par0 ^= 1; }
        }
        // re-arm this buffer's mbar for its next phase (stores at step s+1)
        if (tid == 0) mbar_expect_tx(b ? mb1 : mb0, 1024);

        // matvec: 64 weights vs h[64g .. 64g+64), 4 parallel FMA chains
        const ulonglong2* h2 = (const ulonglong2*)(&hsm[b][g * 68]);
        unsigned long long a0 = 0ull, a1 = 0ull, a2 = 0ull, a3 = 0ull;
#pragma unroll
        for (int q = 0; q < 8; q++) {
            ulonglong2 hv0 = h2[q];
            ulonglong2 hv1 = h2[q + 8];
            a0 = ffma2(wr[2 * q], hv0.x, a0);
            a1 = ffma2(wr[2 * q + 1], hv0.y, a1);
            a2 = ffma2(wr[2 * q + 16], hv1.x, a2);
            a3 = ffma2(wr[2 * q + 17], hv1.y, a3);
        }
        float2 f0 = unpackf2(a0), f1 = unpackf2(a1);
        float2 f2 = unpackf2(a2), f3 = unpackf2(a3);
        float sum = ((f0.x + f0.y) + (f1.x + f1.y)) +
                    ((f2.x + f2.y) + (f3.x + f3.y));
        sum += __shfl_xor_sync(0xffffffffu, sum, 1);
        sum += __shfl_xor_sync(0xffffffffu, sum, 2);
        if (g == 0) sum += p;

        // gather the 4 gate sums of this half-warp's unit (g==0 lanes)
        int base = lane & 16;
        float gi = __shfl_sync(0xffffffffu, sum, base + 0);
        float gf = __shfl_sync(0xffffffffu, sum, base + 4);
        float gc = __shfl_sync(0xffffffffu, sum, base + 8);
        float go = __shfl_sync(0xffffffffu, sum, base + 12);

        float h = 0.f;
        if (producer) {
            float ii = sigmoidf_(gi), ff = sigmoidf_(gf), oo = sigmoidf_(go);
            c = ff * c + ii * tanh_fast(gc);
            h = oo * tanh_fast(c);
        }
        // pair-pack: lane 0 gets lane 16's h (warp-wide shfl = sync point,
        // so sends below are ordered after ALL this warp's hsm[b] reads)
        float h_hi = __shfl_sync(0xffffffffu, h, 16);

        if (lane == 0) {
            unsigned long long pv;
            asm("mov.b64 %0, {%1, %2};" : "=l"(pv) : "f"(h), "f"(h_hi));
            uint32_t slot = hbase + (uint32_t)((b ^ 1) * 272 + koff) * 4u;
            uint32_t mbn = b ? mb0 : mb1;  // step-s stores land on buf b^1
#pragma unroll
            for (int i2 = 0; i2 < 8; i2++) {
                uint32_t ct = ((uint32_t)warp + (uint32_t)i2) & 7u;
                uint32_t ra = mapa_u32(slot, ct);
                uint32_t rm = mapa_u32(mbn, ct);
                st_async_b64(ra, pv, rm);
            }
            *(float2*)&hout[(size_t)t * H_DIM + k_even] = make_float2(h, h_hi);
        }
    }

    // drain: final sends (step T-1, odd) targeted mb0; complete that phase
    mbar_wait(mb0, par0);
    asm volatile("barrier.cluster.arrive.aligned;" ::: "memory");
    asm volatile("barrier.cluster.wait.aligned;" ::: "memory");
}

// ---------------- 3) emit = [hf|hb] @ W_out.T + b_out ----------------------
__global__ __launch_bounds__(128) void emit_kernel(
    const float* __restrict__ Wout, const float* __restrict__ bout) {
    int t = blockIdx.x;
    __shared__ float h[512];
    __shared__ float part[4][18];
    int tid = threadIdx.x;

    h[tid]       = g_h[0][(size_t)t * 256 + tid];
    h[tid + 128] = g_h[0][(size_t)t * 256 + 128 + tid];
    h[tid + 256] = g_h[1][(size_t)t * 256 + tid];
    h[tid + 384] = g_h[1][(size_t)t * 256 + 128 + tid];
    __syncthreads();

    if (tid < 72) {
        int jj = tid >> 2, q = tid & 3;
        const float* w = Wout + (size_t)jj * 512 + q * 128;
        const float* hh = h + q * 128;
        float a0 = 0.f, a1 = 0.f, a2 = 0.f, a3 = 0.f;
#pragma unroll
        for (int k = 0; k < 128; k += 4) {
            a0 += hh[k] * w[k];
            a1 += hh[k + 1] * w[k + 1];
            a2 += hh[k + 2] * w[k + 2];
            a3 += hh[k + 3] * w[k + 3];
        }
        part[q][jj] = (a0 + a1) + (a2 + a3);
    }
    __syncthreads();
    if (tid < 18)
        g_emit[(size_t)t * L_TAGS + tid] =
            part[0][tid] + part[1][tid] + part[2][tid] + part[3][tid] + bout[tid];
}

// ---------------- 4) Viterbi + backtrack (one warp) -------------------------
__global__ void viterbi_kernel(const float* __restrict__ trans,
                               float* __restrict__ out, int write_score) {
    extern __shared__ unsigned char bp[];   // T_LEN * L_TAGS backpointers
    int j = threadIdx.x;
    bool act = (j < L_TAGS);

    float tcol[L_TAGS];
#pragma unroll
    for (int i = 0; i < L_TAGS; i++)
        tcol[i] = act ? trans[i * L_TAGS + j] : 0.f;

    float fv = act ? ((j == START_TAG) ? 0.f : NEGV) : -3.0e38f;
    float e = act ? g_emit[j] : 0.f;

    for (int t = 0; t < T_LEN; t++) {
        float e_next = (act && t + 1 < T_LEN)
                           ? g_emit[(size_t)(t + 1) * L_TAGS + j] : 0.f;
        float b0 = -3.4e38f, b1 = -3.4e38f, b2 = -3.4e38f;
        int a0 = 0, a1 = 6, a2 = 12;
#pragma unroll
        for (int i = 0; i < 6; i++) {
            float s0 = __shfl_sync(0xffffffffu, fv, i) + tcol[i];
            float s1 = __shfl_sync(0xffffffffu, fv, i + 6) + tcol[i + 6];
            float s2 = __shfl_sync(0xffffffffu, fv, i + 12) + tcol[i + 12];
            if (s0 > b0) { b0 = s0; a0 = i; }
            if (s1 > b1) { b1 = s1; a1 = i + 6; }
            if (s2 > b2) { b2 = s2; a2 = i + 12; }
        }
        float best = b0; int arg = a0;
        if (b1 > best) { best = b1; arg = a1; }
        if (b2 > best) { best = b2; arg = a2; }

        if (act) {
            bp[t * L_TAGS + j] = (unsigned char)arg;
            fv = best + e;
        }
        e = e_next;
    }

    float term = act ? (fv + trans[j * L_TAGS + STOP_TAG]) : -3.4e38f;
    int ai = j;
#pragma unroll
    for (int off = 16; off > 0; off >>= 1) {
        float ov = __shfl_xor_sync(0xffffffffu, term, off);
        int oi = __shfl_xor_sync(0xffffffffu, ai, off);
        if (ov > term || (ov == term && oi < ai)) { term = ov; ai = oi; }
    }

    if (j == 0) {
        if (write_score) out[0] = term;
        float* path = out + write_score;
        int tag = ai;
        for (int t = T_LEN - 1; t >= 0; t--) {
            path[t] = (float)tag;
            tag = bp[t * L_TAGS + tag];
        }
    }
}

// ---------------- launch ----------------------------------------------------
extern "C" void kernel_launch(void* const* d_in, const int* in_sizes, int n_in,
                              void* d_out, int out_size) {
    const int*   feats  = (const int*)d_in[0];
    const float* emb    = (const float*)d_in[1];
    const float* w_ih_f = (const float*)d_in[2];
    const float* w_hh_f = (const float*)d_in[3];
    const float* b_f    = (const float*)d_in[4];
    const float* w_ih_b = (const float*)d_in[5];
    const float* w_hh_b = (const float*)d_in[6];
    const float* b_b    = (const float*)d_in[7];
    const float* W_out  = (const float*)d_in[8];
    const float* b_out  = (const float*)d_in[9];
    const float* trans  = (const float*)d_in[10];

    dim3 gg(G_DIM / 64, T_LEN / 64, 2);
    gemm_pre_kernel<<<gg, 256>>>(feats, emb, w_ih_f, w_ih_b, b_f, b_b);

    lstm_cluster_kernel<<<16, 512>>>(w_hh_f, w_hh_b);

    emit_kernel<<<T_LEN, 128>>>(W_out, b_out);

    int ws = (out_size > T_LEN) ? 1 : 0;   // layout: [path_score, path...]
    static int smem_set = 0;
    if (!smem_set) {
        cudaFuncSetAttribute(viterbi_kernel,
                             cudaFuncAttributeMaxDynamicSharedMemorySize,
                             T_LEN * L_TAGS + 1024);
        smem_set = 1;
    }
    viterbi_kernel<<<1, 32, T_LEN * L_TAGS>>>(trans, (float*)d_out, ws);
}